// round 14
// baseline (speedup 1.0000x reference)
#include <cuda_runtime.h>
#include <cuda_bf16.h>

// HydraGNN: 2x SAGEConv(mean) + MLP head, fp32.
// R14: atomic-free scatter (hist records per-edge rank; scatter = row_start
// gather + plain store), bf16 staged x for agg1 (128B rows), p back to fp32
// for error margin. Broadcast-index aggregation, f32x2 GEMMs.

#define NN 50000
#define NE 800000
#define CHUNK 512
#define NCHUNK ((NN + CHUNK - 1) / CHUNK)   // 98

typedef unsigned long long ull;

__device__ int g_counts[NN];
__device__ int g_row_start[NN + 1];
__device__ int g_rank[NE];
__device__ int g_csr_src[NE];
__device__ __align__(16) unsigned g_xb[NN * 32];  // x in bf16: 64ch = 128B/row
__device__ __align__(16) float g_mean[NN * 64];   // layer-1 mean (fp32)
__device__ __align__(16) float g_h1[NN * 64];     // relu(layer1)
__device__ __align__(16) float g_p[NN * 32];      // h1 @ w2_l (fp32)
__device__ __align__(16) float g_mean2[NN * 32];  // mean of p (fp32)

// ---------------------------------------------------------------- helpers
__device__ __forceinline__ ull ffma2(ull a, ull b, ull c) {
    ull d;
    asm("fma.rn.f32x2 %0, %1, %2, %3;" : "=l"(d) : "l"(a), "l"(b), "l"(c));
    return d;
}
__device__ __forceinline__ ull dup2(float v) {
    ull r; unsigned u = __float_as_uint(v);
    asm("mov.b64 %0, {%1, %1};" : "=l"(r) : "r"(u));
    return r;
}
__device__ __forceinline__ ull pack2(float lo, float hi) {
    ull r;
    asm("mov.b64 %0, {%1, %2};" : "=l"(r)
        : "r"(__float_as_uint(lo)), "r"(__float_as_uint(hi)));
    return r;
}
__device__ __forceinline__ float lo32(ull a) { return __uint_as_float((unsigned)a); }
__device__ __forceinline__ float hi32(ull a) { return __uint_as_float((unsigned)(a >> 32)); }
union F4U { float4 f4; ull u[2]; float f[4]; };

__device__ __forceinline__ unsigned f2_to_bf2(float lo, float hi) {
    __nv_bfloat162 h = __float22bfloat162_rn(make_float2(lo, hi));
    return *(unsigned*)&h;
}
__device__ __forceinline__ float2 bf2_to_f2(unsigned u) {
    __nv_bfloat162 h = *(__nv_bfloat162*)&u;
    return __bfloat1622float2(h);
}
__device__ __forceinline__ void accbf8(float4& a, float4& b, const uint4& v) {
    float2 f;
    f = bf2_to_f2(v.x); a.x += f.x; a.y += f.y;
    f = bf2_to_f2(v.y); a.z += f.x; a.w += f.y;
    f = bf2_to_f2(v.z); b.x += f.x; b.y += f.y;
    f = bf2_to_f2(v.w); b.z += f.x; b.w += f.y;
}
__device__ __forceinline__ void acc4(float4& a, const float4& v) {
    a.x += v.x; a.y += v.y; a.z += v.z; a.w += v.w;
}

// ------------------------------------------------------------ x -> bf16
__global__ void k_tobf16(const float4* __restrict__ x4) {
    int i = blockIdx.x * blockDim.x + threadIdx.x;   // one uint4 out = 8 floats in
    if (i < NN * 8) {
        float4 a = x4[2 * i];
        float4 b = x4[2 * i + 1];
        uint4 o;
        o.x = f2_to_bf2(a.x, a.y);
        o.y = f2_to_bf2(a.z, a.w);
        o.z = f2_to_bf2(b.x, b.y);
        o.w = f2_to_bf2(b.z, b.w);
        ((uint4*)g_xb)[i] = o;
    }
}

// ---------------------------------------------------------------- CSR build
// hist: count per node AND record each edge's within-node rank (atomic return).
__global__ void k_hist(const int4* __restrict__ dst4) {
    int e = blockIdx.x * blockDim.x + threadIdx.x;
    if (e < NE / 4) {
        int4 d = dst4[e];
        int4 r;
        r.x = atomicAdd(&g_counts[d.x], 1);
        r.y = atomicAdd(&g_counts[d.y], 1);
        r.z = atomicAdd(&g_counts[d.z], 1);
        r.w = atomicAdd(&g_counts[d.w], 1);
        ((int4*)g_rank)[e] = r;
    }
}

__global__ __launch_bounds__(CHUNK) void k_scan() {
    __shared__ int sh[CHUNK];
    __shared__ int s_prefix;
    int b = blockIdx.x, t = threadIdx.x;
    int base = b * CHUNK;
    int partial = 0;
    for (int k = t; k < base; k += CHUNK) partial += g_counts[k];
    sh[t] = partial;
    __syncthreads();
#pragma unroll
    for (int off = CHUNK >> 1; off > 0; off >>= 1) {
        if (t < off) sh[t] += sh[t + off];
        __syncthreads();
    }
    if (t == 0) s_prefix = sh[0];
    __syncthreads();

    int i = base + t;
    int v = (i < NN) ? g_counts[i] : 0;
    sh[t] = v;
    __syncthreads();
#pragma unroll
    for (int off = 1; off < CHUNK; off <<= 1) {
        int tv = (t >= off) ? sh[t - off] : 0;
        __syncthreads();
        sh[t] += tv;
        __syncthreads();
    }
    if (i < NN) g_row_start[i] = s_prefix + sh[t] - v;
    if (b == NCHUNK - 1 && t == CHUNK - 1) g_row_start[NN] = NE;
}

// scatter WITHOUT atomics: pos = row_start[dst] + rank (rank from hist).
__global__ void k_scatter(const int4* __restrict__ src4,
                          const int4* __restrict__ dst4) {
    int e = blockIdx.x * blockDim.x + threadIdx.x;
    if (e < NE / 4) {
        int4 s = src4[e];
        int4 d = dst4[e];
        int4 r = ((const int4*)g_rank)[e];
        int p0 = __ldg(&g_row_start[d.x]) + r.x;
        int p1 = __ldg(&g_row_start[d.y]) + r.y;
        int p2 = __ldg(&g_row_start[d.z]) + r.z;
        int p3 = __ldg(&g_row_start[d.w]) + r.w;
        g_csr_src[p0] = s.x;
        g_csr_src[p1] = s.y;
        g_csr_src[p2] = s.z;
        g_csr_src[p3] = s.w;
    }
}

// ---------------------------------------------------- layer-1 aggregation
// Warp per node, bf16 rows (128B). Broadcast-index; quarter-warp per edge
// (lane = e4*8 + c8): one LDG.128 covers 4 edges; fp32 accumulation.
__global__ __launch_bounds__(256) void k_aggregate1() {
    int w = (blockIdx.x * blockDim.x + threadIdx.x) >> 5;
    if (w >= NN) return;
    int lane = threadIdx.x & 31;
    int e4 = lane >> 3;          // 0..3: edge slot
    int c8 = lane & 7;           // uint4 chunk -> channels [8*c8, 8*c8+8)

    int s = __ldg(&g_row_start[w]), e = __ldg(&g_row_start[w + 1]);
    float4 a0 = make_float4(0.f, 0.f, 0.f, 0.f);
    float4 a1 = make_float4(0.f, 0.f, 0.f, 0.f);
    float4 b0 = make_float4(0.f, 0.f, 0.f, 0.f);
    float4 b1 = make_float4(0.f, 0.f, 0.f, 0.f);

    for (int base = s; base < e; base += 32) {
        int n = e - base; if (n > 32) n = 32;
        int myidx = 0;
        if (base + lane < e) myidx = __ldg(&g_csr_src[base + lane]);
        for (int t2 = 0; t2 < n; t2 += 8) {
            int ta = t2 + e4;
            int tb = t2 + 4 + e4;
            int ia = __shfl_sync(0xffffffffu, myidx, ta & 31);
            int ib = __shfl_sync(0xffffffffu, myidx, tb & 31);
            if (ta < n) {
                uint4 v = ((const uint4*)(g_xb + (size_t)ia * 32))[c8];
                accbf8(a0, a1, v);
            }
            if (tb < n) {
                uint4 v = ((const uint4*)(g_xb + (size_t)ib * 32))[c8];
                accbf8(b0, b1, v);
            }
        }
    }
    a0.x += b0.x; a0.y += b0.y; a0.z += b0.z; a0.w += b0.w;
    a1.x += b1.x; a1.y += b1.y; a1.z += b1.z; a1.w += b1.w;
#pragma unroll
    for (int off = 8; off <= 16; off <<= 1) {
        a0.x += __shfl_xor_sync(0xffffffffu, a0.x, off);
        a0.y += __shfl_xor_sync(0xffffffffu, a0.y, off);
        a0.z += __shfl_xor_sync(0xffffffffu, a0.z, off);
        a0.w += __shfl_xor_sync(0xffffffffu, a0.w, off);
        a1.x += __shfl_xor_sync(0xffffffffu, a1.x, off);
        a1.y += __shfl_xor_sync(0xffffffffu, a1.y, off);
        a1.z += __shfl_xor_sync(0xffffffffu, a1.z, off);
        a1.w += __shfl_xor_sync(0xffffffffu, a1.w, off);
    }
    if (lane < 8) {
        float inv = 1.0f / fmaxf((float)(e - s), 1.0f);
        float4* o = (float4*)(g_mean + (size_t)w * 64 + c8 * 8);
        o[0] = make_float4(a0.x * inv, a0.y * inv, a0.z * inv, a0.w * inv);
        o[1] = make_float4(a1.x * inv, a1.y * inv, a1.z * inv, a1.w * inv);
    }
}

// ---------------------------------------------------- layer-2 aggregation
// fp32 p rows (128B). Broadcast-index; quarter-warp per edge
// (lane = e4*8 + c8): one LDG.128 covers 4 edges.
__global__ __launch_bounds__(256) void k_aggregate2() {
    int w = (blockIdx.x * blockDim.x + threadIdx.x) >> 5;
    if (w >= NN) return;
    int lane = threadIdx.x & 31;
    int e4 = lane >> 3;          // 0..3
    int c8 = lane & 7;           // channels [4*c8, 4*c8+4)

    int s = __ldg(&g_row_start[w]), e = __ldg(&g_row_start[w + 1]);
    float4 a0 = make_float4(0.f, 0.f, 0.f, 0.f);
    float4 a1 = make_float4(0.f, 0.f, 0.f, 0.f);

    for (int base = s; base < e; base += 32) {
        int n = e - base; if (n > 32) n = 32;
        int myidx = 0;
        if (base + lane < e) myidx = __ldg(&g_csr_src[base + lane]);
        for (int t2 = 0; t2 < n; t2 += 8) {
            int ta = t2 + e4;
            int tb = t2 + 4 + e4;
            int ia = __shfl_sync(0xffffffffu, myidx, ta & 31);
            int ib = __shfl_sync(0xffffffffu, myidx, tb & 31);
            if (ta < n) {
                float4 v = ((const float4*)(g_p + (size_t)ia * 32))[c8];
                acc4(a0, v);
            }
            if (tb < n) {
                float4 v = ((const float4*)(g_p + (size_t)ib * 32))[c8];
                acc4(a1, v);
            }
        }
    }
    acc4(a0, a1);
#pragma unroll
    for (int off = 8; off <= 16; off <<= 1) {
        a0.x += __shfl_xor_sync(0xffffffffu, a0.x, off);
        a0.y += __shfl_xor_sync(0xffffffffu, a0.y, off);
        a0.z += __shfl_xor_sync(0xffffffffu, a0.z, off);
        a0.w += __shfl_xor_sync(0xffffffffu, a0.w, off);
    }
    if (lane < 8) {
        float inv = 1.0f / fmaxf((float)(e - s), 1.0f);
        float4 r = make_float4(a0.x * inv, a0.y * inv, a0.z * inv, a0.w * inv);
        ((float4*)(g_mean2 + (size_t)w * 32))[c8] = r;
    }
}

// ------------------------------------------------------------- update GEMMs
// h1 = relu(mean @ w1_l + x @ w1_r + b1);  p = h1 @ w2_l  (fp32, f32x2)
__global__ __launch_bounds__(128) void k_update1(const float* __restrict__ x,
                                                 const float* __restrict__ wl,
                                                 const float* __restrict__ wr,
                                                 const float* __restrict__ b,
                                                 const float* __restrict__ w2l) {
    __shared__ float s_wl[64 * 64], s_wr[64 * 64], s_w2l[64 * 32], s_b[64];
    for (int idx = threadIdx.x; idx < 4096; idx += 128) {
        s_wl[idx] = wl[idx];
        s_wr[idx] = wr[idx];
    }
    for (int idx = threadIdx.x; idx < 2048; idx += 128) s_w2l[idx] = w2l[idx];
    if (threadIdx.x < 64) s_b[threadIdx.x] = b[threadIdx.x];
    __syncthreads();

    int i = blockIdx.x * blockDim.x + threadIdx.x;
    if (i >= NN) return;
    const float* m  = g_mean + (size_t)i * 64;
    const float* xi = x      + (size_t)i * 64;

    ull acc[32];
#pragma unroll
    for (int jj = 0; jj < 16; jj++) {
        F4U b4; b4.f4 = ((const float4*)s_b)[jj];
        acc[2 * jj]     = b4.u[0];
        acc[2 * jj + 1] = b4.u[1];
    }

    for (int kb = 0; kb < 64; kb += 4) {
        float4 mv4 = *(const float4*)(m + kb);
        float4 xv4 = *(const float4*)(xi + kb);
        float mvs[4] = {mv4.x, mv4.y, mv4.z, mv4.w};
        float xvs[4] = {xv4.x, xv4.y, xv4.z, xv4.w};
#pragma unroll
        for (int kk = 0; kk < 4; kk++) {
            int k = kb + kk;
            ull mv2 = dup2(mvs[kk]);
            ull xv2 = dup2(xvs[kk]);
            const float4* wl4 = (const float4*)(s_wl + k * 64);
            const float4* wr4 = (const float4*)(s_wr + k * 64);
#pragma unroll
            for (int jj = 0; jj < 16; jj++) {
                F4U wa; wa.f4 = wl4[jj];
                F4U wb; wb.f4 = wr4[jj];
                acc[2 * jj]     = ffma2(wa.u[0], mv2, acc[2 * jj]);
                acc[2 * jj + 1] = ffma2(wa.u[1], mv2, acc[2 * jj + 1]);
                acc[2 * jj]     = ffma2(wb.u[0], xv2, acc[2 * jj]);
                acc[2 * jj + 1] = ffma2(wb.u[1], xv2, acc[2 * jj + 1]);
            }
        }
    }

    // relu -> store h1; fused p = h1 @ w2_l
    ull p[16];
#pragma unroll
    for (int jj = 0; jj < 16; jj++) p[jj] = 0ULL;

    float* oh = g_h1 + (size_t)i * 64;
#pragma unroll
    for (int jj = 0; jj < 32; jj++) {
        float lo = fmaxf(lo32(acc[jj]), 0.f);
        float hi = fmaxf(hi32(acc[jj]), 0.f);
        *(float2*)(oh + 2 * jj) = make_float2(lo, hi);
        ull hlo = dup2(lo), hhi = dup2(hi);
        const float4* wlo = (const float4*)(s_w2l + (2 * jj) * 32);
        const float4* whi = (const float4*)(s_w2l + (2 * jj + 1) * 32);
#pragma unroll
        for (int t = 0; t < 8; t++) {
            F4U wa; wa.f4 = wlo[t];
            F4U wb; wb.f4 = whi[t];
            p[2 * t]     = ffma2(wa.u[0], hlo, p[2 * t]);
            p[2 * t + 1] = ffma2(wa.u[1], hlo, p[2 * t + 1]);
            p[2 * t]     = ffma2(wb.u[0], hhi, p[2 * t]);
            p[2 * t + 1] = ffma2(wb.u[1], hhi, p[2 * t + 1]);
        }
    }
    float* op = g_p + (size_t)i * 32;
#pragma unroll
    for (int t = 0; t < 16; t++)
        *(float2*)(op + 2 * t) = make_float2(lo32(p[t]), hi32(p[t]));
}

// h2 = relu(mean2 + b2 + h1 @ w2_r); out = relu(h2@wc1+bc1)@wc2 + bc2
__global__ __launch_bounds__(128) void k_update2(const float* __restrict__ w2r,
                                                 const float* __restrict__ b2,
                                                 const float* __restrict__ wc1,
                                                 const float* __restrict__ bc1,
                                                 const float* __restrict__ wc2,
                                                 const float* __restrict__ bc2,
                                                 float* __restrict__ out) {
    __shared__ float s_wr[64 * 32], s_b2[32];
    __shared__ float s_wc1[32 * 16], s_bc1[16], s_wc2[16 * 2], s_bc2[2];
    for (int idx = threadIdx.x; idx < 2048; idx += 128) s_wr[idx] = w2r[idx];
    for (int idx = threadIdx.x; idx < 512; idx += 128) s_wc1[idx] = wc1[idx];
    if (threadIdx.x < 32) s_b2[threadIdx.x]  = b2[threadIdx.x];
    if (threadIdx.x < 32) s_wc2[threadIdx.x] = wc2[threadIdx.x];
    if (threadIdx.x < 16) s_bc1[threadIdx.x] = bc1[threadIdx.x];
    if (threadIdx.x < 2)  s_bc2[threadIdx.x] = bc2[threadIdx.x];
    __syncthreads();

    int i = blockIdx.x * blockDim.x + threadIdx.x;
    if (i >= NN) return;
    const float* m2 = g_mean2 + (size_t)i * 32;
    const float* hi = g_h1    + (size_t)i * 64;

    ull acc[16];
#pragma unroll
    for (int jj = 0; jj < 8; jj++) {
        F4U m4; m4.f4 = ((const float4*)m2)[jj];
        F4U b4; b4.f4 = ((const float4*)s_b2)[jj];
        acc[2 * jj]     = pack2(m4.f[0] + b4.f[0], m4.f[1] + b4.f[1]);
        acc[2 * jj + 1] = pack2(m4.f[2] + b4.f[2], m4.f[3] + b4.f[3]);
    }

    for (int kb = 0; kb < 64; kb += 4) {
        float4 hv4 = *(const float4*)(hi + kb);
        float hvs[4] = {hv4.x, hv4.y, hv4.z, hv4.w};
#pragma unroll
        for (int kk = 0; kk < 4; kk++) {
            ull hv2 = dup2(hvs[kk]);
            const float4* wr4 = (const float4*)(s_wr + (kb + kk) * 32);
#pragma unroll
            for (int t = 0; t < 8; t++) {
                F4U wa; wa.f4 = wr4[t];
                acc[2 * t]     = ffma2(wa.u[0], hv2, acc[2 * t]);
                acc[2 * t + 1] = ffma2(wa.u[1], hv2, acc[2 * t + 1]);
            }
        }
    }

    // classifier head
    ull c1[8];
#pragma unroll
    for (int t = 0; t < 4; t++) {
        F4U b4; b4.f4 = ((const float4*)s_bc1)[t];
        c1[2 * t]     = b4.u[0];
        c1[2 * t + 1] = b4.u[1];
    }
#pragma unroll
    for (int jj = 0; jj < 16; jj++) {
        float lo = fmaxf(lo32(acc[jj]), 0.f);
        float hi2 = fmaxf(hi32(acc[jj]), 0.f);
        ull hlo = dup2(lo), hhi = dup2(hi2);
        const float4* wlo = (const float4*)(s_wc1 + (2 * jj) * 16);
        const float4* whi = (const float4*)(s_wc1 + (2 * jj + 1) * 16);
#pragma unroll
        for (int t = 0; t < 4; t++) {
            F4U wa; wa.f4 = wlo[t];
            F4U wb; wb.f4 = whi[t];
            c1[2 * t]     = ffma2(wa.u[0], hlo, c1[2 * t]);
            c1[2 * t + 1] = ffma2(wa.u[1], hlo, c1[2 * t + 1]);
            c1[2 * t]     = ffma2(wb.u[0], hhi, c1[2 * t]);
            c1[2 * t + 1] = ffma2(wb.u[1], hhi, c1[2 * t + 1]);
        }
    }
    float o0 = s_bc2[0], o1 = s_bc2[1];
#pragma unroll
    for (int t = 0; t < 8; t++) {
        float h0 = fmaxf(lo32(c1[t]), 0.f);
        float h1v = fmaxf(hi32(c1[t]), 0.f);
        o0 += h0 * s_wc2[(2 * t) * 2 + 0] + h1v * s_wc2[(2 * t + 1) * 2 + 0];
        o1 += h0 * s_wc2[(2 * t) * 2 + 1] + h1v * s_wc2[(2 * t + 1) * 2 + 1];
    }
    *(float2*)(out + (size_t)i * 2) = make_float2(o0, o1);
}

// ------------------------------------------------------------------- launch
extern "C" void kernel_launch(void* const* d_in, const int* in_sizes, int n_in,
                              void* d_out, int out_size) {
    const float* x    = (const float*)d_in[0];
    const int*   ei   = (const int*)d_in[1];
    const int4*  src4 = (const int4*)ei;
    const int4*  dst4 = (const int4*)(ei + NE);
    const float* w1l = (const float*)d_in[2];
    const float* w1r = (const float*)d_in[3];
    const float* b1  = (const float*)d_in[4];
    const float* w2l = (const float*)d_in[5];
    const float* w2r = (const float*)d_in[6];
    const float* b2  = (const float*)d_in[7];
    const float* wc1 = (const float*)d_in[8];
    const float* bc1 = (const float*)d_in[9];
    const float* wc2 = (const float*)d_in[10];
    const float* bc2 = (const float*)d_in[11];
    float* out = (float*)d_out;

    // x -> bf16 staging (independent of CSR)
    k_tobf16<<<(NN * 8 + 255) / 256, 256>>>((const float4*)x);

    // CSR build: memset + hist(+rank) + scan + atomic-free scatter
    void* cp = nullptr;
    cudaGetSymbolAddress(&cp, g_counts);
    cudaMemsetAsync(cp, 0, NN * sizeof(int));
    k_hist<<<(NE / 4 + 255) / 256, 256>>>(dst4);
    k_scan<<<NCHUNK, CHUNK>>>();
    k_scatter<<<(NE / 4 + 255) / 256, 256>>>(src4, dst4);

    // Layer 1 (+ fused p = h1 @ w2_l)
    k_aggregate1<<<(NN * 32 + 255) / 256, 256>>>();
    k_update1<<<(NN + 127) / 128, 128>>>(x, w1l, w1r, b1, w2l);

    // Layer 2 + classifier
    k_aggregate2<<<(NN * 32 + 255) / 256, 256>>>();
    k_update2<<<(NN + 127) / 128, 128>>>(w2r, b2, wc1, bc1, wc2, bc2, out);
}

// round 15
// speedup vs baseline: 1.0489x; 1.0489x over previous
#include <cuda_runtime.h>
#include <cuda_fp16.h>

// HydraGNN: 2x SAGEConv(mean) + MLP head, fp32.
// R15 = R13 structure with fp16 staging (8x less quant error than bf16, same
// bytes), staging+hist fused into one kernel, scatter with 8 independent
// atomic chains per thread. Broadcast-index aggregation, f32x2 GEMMs.

#define NN 50000
#define NE 800000
#define CHUNK 512
#define NCHUNK ((NN + CHUNK - 1) / CHUNK)   // 98

typedef unsigned long long ull;

__device__ int g_counts[NN];
__device__ int g_row_start[NN + 1];
__device__ int g_row_fill[NN];
__device__ int g_csr_src[NE];
__device__ __align__(16) unsigned g_xh[NN * 32];  // x in fp16: 64ch = 128B/row
__device__ __align__(16) unsigned g_ph[NN * 16];  // p in fp16: 32ch = 64B/row
__device__ __align__(16) float g_mean[NN * 64];   // layer-1 mean (fp32)
__device__ __align__(16) float g_h1[NN * 64];     // relu(layer1)
__device__ __align__(16) float g_mean2[NN * 32];  // mean of p (fp32)

// ---------------------------------------------------------------- helpers
__device__ __forceinline__ ull ffma2(ull a, ull b, ull c) {
    ull d;
    asm("fma.rn.f32x2 %0, %1, %2, %3;" : "=l"(d) : "l"(a), "l"(b), "l"(c));
    return d;
}
__device__ __forceinline__ ull dup2(float v) {
    ull r; unsigned u = __float_as_uint(v);
    asm("mov.b64 %0, {%1, %1};" : "=l"(r) : "r"(u));
    return r;
}
__device__ __forceinline__ ull pack2(float lo, float hi) {
    ull r;
    asm("mov.b64 %0, {%1, %2};" : "=l"(r)
        : "r"(__float_as_uint(lo)), "r"(__float_as_uint(hi)));
    return r;
}
__device__ __forceinline__ float lo32(ull a) { return __uint_as_float((unsigned)a); }
__device__ __forceinline__ float hi32(ull a) { return __uint_as_float((unsigned)(a >> 32)); }
union F4U { float4 f4; ull u[2]; float f[4]; };

__device__ __forceinline__ unsigned f2_to_h2(float lo, float hi) {
    __half2 h = __float22half2_rn(make_float2(lo, hi));
    return *(unsigned*)&h;
}
__device__ __forceinline__ float2 h2_to_f2(unsigned u) {
    __half2 h = *(__half2*)&u;
    return __half22float2(h);
}
// accumulate 8 fp16 channels (one uint4) into two float4 accumulators
__device__ __forceinline__ void acch8(float4& a, float4& b, const uint4& v) {
    float2 f;
    f = h2_to_f2(v.x); a.x += f.x; a.y += f.y;
    f = h2_to_f2(v.y); a.z += f.x; a.w += f.y;
    f = h2_to_f2(v.z); b.x += f.x; b.y += f.y;
    f = h2_to_f2(v.w); b.z += f.x; b.w += f.y;
}

// --------------------------------------------- fused x->fp16 staging + hist
// Two independent jobs share one launch (saves a graph node):
//   threads [0, NN*8):  convert 8 floats of x to fp16 (one uint4 store)
//   threads [0, NE/4):  histogram 4 dst indices (REDG — result discarded)
__global__ void k_stage_hist(const float4* __restrict__ x4,
                             const int4* __restrict__ dst4) {
    int i = blockIdx.x * blockDim.x + threadIdx.x;
    if (i < NN * 8) {
        float4 a = x4[2 * i];
        float4 b = x4[2 * i + 1];
        uint4 o;
        o.x = f2_to_h2(a.x, a.y);
        o.y = f2_to_h2(a.z, a.w);
        o.z = f2_to_h2(b.x, b.y);
        o.w = f2_to_h2(b.z, b.w);
        ((uint4*)g_xh)[i] = o;
    }
    if (i < NE / 4) {
        int4 d = dst4[i];
        atomicAdd(&g_counts[d.x], 1);
        atomicAdd(&g_counts[d.y], 1);
        atomicAdd(&g_counts[d.z], 1);
        atomicAdd(&g_counts[d.w], 1);
    }
}

// ---------------------------------------------------------------- CSR build
__global__ __launch_bounds__(CHUNK) void k_scan() {
    __shared__ int sh[CHUNK];
    __shared__ int s_prefix;
    int b = blockIdx.x, t = threadIdx.x;
    int base = b * CHUNK;
    int partial = 0;
    for (int k = t; k < base; k += CHUNK) partial += g_counts[k];
    sh[t] = partial;
    __syncthreads();
#pragma unroll
    for (int off = CHUNK >> 1; off > 0; off >>= 1) {
        if (t < off) sh[t] += sh[t + off];
        __syncthreads();
    }
    if (t == 0) s_prefix = sh[0];
    __syncthreads();

    int i = base + t;
    int v = (i < NN) ? g_counts[i] : 0;
    sh[t] = v;
    __syncthreads();
#pragma unroll
    for (int off = 1; off < CHUNK; off <<= 1) {
        int tv = (t >= off) ? sh[t - off] : 0;
        __syncthreads();
        sh[t] += tv;
        __syncthreads();
    }
    if (i < NN) {
        int excl = s_prefix + sh[t] - v;
        g_row_start[i] = excl;
        g_row_fill[i]  = excl;
    }
    if (b == NCHUNK - 1 && t == CHUNK - 1) g_row_start[NN] = NE;
}

// Scatter: 8 edges per thread (two int4 quads) -> 8 independent
// atomic+store chains in flight (latency-bound kernel, issue was 1.4%).
__global__ void k_scatter(const int4* __restrict__ src4,
                          const int4* __restrict__ dst4) {
    int e = blockIdx.x * blockDim.x + threadIdx.x;
    if (e < NE / 8) {
        int4 s0 = src4[e],          d0 = dst4[e];
        int4 s1 = src4[e + NE / 8], d1 = dst4[e + NE / 8];
        int p0 = atomicAdd(&g_row_fill[d0.x], 1);
        int p1 = atomicAdd(&g_row_fill[d0.y], 1);
        int p2 = atomicAdd(&g_row_fill[d0.z], 1);
        int p3 = atomicAdd(&g_row_fill[d0.w], 1);
        int p4 = atomicAdd(&g_row_fill[d1.x], 1);
        int p5 = atomicAdd(&g_row_fill[d1.y], 1);
        int p6 = atomicAdd(&g_row_fill[d1.z], 1);
        int p7 = atomicAdd(&g_row_fill[d1.w], 1);
        g_csr_src[p0] = s0.x;
        g_csr_src[p1] = s0.y;
        g_csr_src[p2] = s0.z;
        g_csr_src[p3] = s0.w;
        g_csr_src[p4] = s1.x;
        g_csr_src[p5] = s1.y;
        g_csr_src[p6] = s1.z;
        g_csr_src[p7] = s1.w;
    }
}

// ---------------------------------------------------- layer-1 aggregation
// Warp per node, fp16 rows (128B). Broadcast-index: one coalesced LDG per 32
// CSR indices, SHFL distributes. Quarter-warp per edge (lane = e4*8 + c8):
// one LDG.128 covers 4 edges; fp32 accumulation.
__global__ __launch_bounds__(256) void k_aggregate1() {
    int w = (blockIdx.x * blockDim.x + threadIdx.x) >> 5;
    if (w >= NN) return;
    int lane = threadIdx.x & 31;
    int e4 = lane >> 3;          // 0..3: edge slot
    int c8 = lane & 7;           // uint4 chunk -> channels [8*c8, 8*c8+8)

    int s = __ldg(&g_row_start[w]), e = __ldg(&g_row_start[w + 1]);
    float4 a0 = make_float4(0.f, 0.f, 0.f, 0.f);
    float4 a1 = make_float4(0.f, 0.f, 0.f, 0.f);
    float4 b0 = make_float4(0.f, 0.f, 0.f, 0.f);
    float4 b1 = make_float4(0.f, 0.f, 0.f, 0.f);

    for (int base = s; base < e; base += 32) {
        int n = e - base; if (n > 32) n = 32;
        int myidx = 0;
        if (base + lane < e) myidx = __ldg(&g_csr_src[base + lane]);
        for (int t2 = 0; t2 < n; t2 += 8) {
            int ta = t2 + e4;
            int tb = t2 + 4 + e4;
            int ia = __shfl_sync(0xffffffffu, myidx, ta & 31);
            int ib = __shfl_sync(0xffffffffu, myidx, tb & 31);
            if (ta < n) {
                uint4 v = ((const uint4*)(g_xh + (size_t)ia * 32))[c8];
                acch8(a0, a1, v);
            }
            if (tb < n) {
                uint4 v = ((const uint4*)(g_xh + (size_t)ib * 32))[c8];
                acch8(b0, b1, v);
            }
        }
    }
    a0.x += b0.x; a0.y += b0.y; a0.z += b0.z; a0.w += b0.w;
    a1.x += b1.x; a1.y += b1.y; a1.z += b1.z; a1.w += b1.w;
#pragma unroll
    for (int off = 8; off <= 16; off <<= 1) {
        a0.x += __shfl_xor_sync(0xffffffffu, a0.x, off);
        a0.y += __shfl_xor_sync(0xffffffffu, a0.y, off);
        a0.z += __shfl_xor_sync(0xffffffffu, a0.z, off);
        a0.w += __shfl_xor_sync(0xffffffffu, a0.w, off);
        a1.x += __shfl_xor_sync(0xffffffffu, a1.x, off);
        a1.y += __shfl_xor_sync(0xffffffffu, a1.y, off);
        a1.z += __shfl_xor_sync(0xffffffffu, a1.z, off);
        a1.w += __shfl_xor_sync(0xffffffffu, a1.w, off);
    }
    if (lane < 8) {
        float inv = 1.0f / fmaxf((float)(e - s), 1.0f);
        float4* o = (float4*)(g_mean + (size_t)w * 64 + c8 * 8);
        o[0] = make_float4(a0.x * inv, a0.y * inv, a0.z * inv, a0.w * inv);
        o[1] = make_float4(a1.x * inv, a1.y * inv, a1.z * inv, a1.w * inv);
    }
}

// ---------------------------------------------------- layer-2 aggregation
// Warp per node, fp16 p rows (64B). Eighth-warp per edge (lane = e8*4 + c4):
// one LDG.128 covers 8 edges; fp32 accumulation.
__global__ __launch_bounds__(256) void k_aggregate2() {
    int w = (blockIdx.x * blockDim.x + threadIdx.x) >> 5;
    if (w >= NN) return;
    int lane = threadIdx.x & 31;
    int e8 = lane >> 2;          // 0..7: edge slot
    int c4 = lane & 3;           // uint4 chunk -> channels [8*c4, 8*c4+8)

    int s = __ldg(&g_row_start[w]), e = __ldg(&g_row_start[w + 1]);
    float4 a0 = make_float4(0.f, 0.f, 0.f, 0.f);
    float4 a1 = make_float4(0.f, 0.f, 0.f, 0.f);
    float4 b0 = make_float4(0.f, 0.f, 0.f, 0.f);
    float4 b1 = make_float4(0.f, 0.f, 0.f, 0.f);

    for (int base = s; base < e; base += 32) {
        int n = e - base; if (n > 32) n = 32;
        int myidx = 0;
        if (base + lane < e) myidx = __ldg(&g_csr_src[base + lane]);
        for (int t2 = 0; t2 < n; t2 += 16) {
            int ta = t2 + e8;
            int tb = t2 + 8 + e8;
            int ia = __shfl_sync(0xffffffffu, myidx, ta & 31);
            int ib = __shfl_sync(0xffffffffu, myidx, tb & 31);
            if (ta < n) {
                uint4 v = ((const uint4*)(g_ph + (size_t)ia * 16))[c4];
                acch8(a0, a1, v);
            }
            if (tb < n) {
                uint4 v = ((const uint4*)(g_ph + (size_t)ib * 16))[c4];
                acch8(b0, b1, v);
            }
        }
    }
    a0.x += b0.x; a0.y += b0.y; a0.z += b0.z; a0.w += b0.w;
    a1.x += b1.x; a1.y += b1.y; a1.z += b1.z; a1.w += b1.w;
#pragma unroll
    for (int off = 4; off <= 16; off <<= 1) {
        a0.x += __shfl_xor_sync(0xffffffffu, a0.x, off);
        a0.y += __shfl_xor_sync(0xffffffffu, a0.y, off);
        a0.z += __shfl_xor_sync(0xffffffffu, a0.z, off);
        a0.w += __shfl_xor_sync(0xffffffffu, a0.w, off);
        a1.x += __shfl_xor_sync(0xffffffffu, a1.x, off);
        a1.y += __shfl_xor_sync(0xffffffffu, a1.y, off);
        a1.z += __shfl_xor_sync(0xffffffffu, a1.z, off);
        a1.w += __shfl_xor_sync(0xffffffffu, a1.w, off);
    }
    if (lane < 4) {
        float inv = 1.0f / fmaxf((float)(e - s), 1.0f);
        float4* o = (float4*)(g_mean2 + (size_t)w * 32 + c4 * 8);
        o[0] = make_float4(a0.x * inv, a0.y * inv, a0.z * inv, a0.w * inv);
        o[1] = make_float4(a1.x * inv, a1.y * inv, a1.z * inv, a1.w * inv);
    }
}

// ------------------------------------------------------------- update GEMMs
// h1 = relu(mean @ w1_l + x @ w1_r + b1);  p = h1 @ w2_l  (stored fp16)
__global__ __launch_bounds__(128) void k_update1(const float* __restrict__ x,
                                                 const float* __restrict__ wl,
                                                 const float* __restrict__ wr,
                                                 const float* __restrict__ b,
                                                 const float* __restrict__ w2l) {
    __shared__ float s_wl[64 * 64], s_wr[64 * 64], s_w2l[64 * 32], s_b[64];
    for (int idx = threadIdx.x; idx < 4096; idx += 128) {
        s_wl[idx] = wl[idx];
        s_wr[idx] = wr[idx];
    }
    for (int idx = threadIdx.x; idx < 2048; idx += 128) s_w2l[idx] = w2l[idx];
    if (threadIdx.x < 64) s_b[threadIdx.x] = b[threadIdx.x];
    __syncthreads();

    int i = blockIdx.x * blockDim.x + threadIdx.x;
    if (i >= NN) return;
    const float* m  = g_mean + (size_t)i * 64;
    const float* xi = x      + (size_t)i * 64;

    ull acc[32];
#pragma unroll
    for (int jj = 0; jj < 16; jj++) {
        F4U b4; b4.f4 = ((const float4*)s_b)[jj];
        acc[2 * jj]     = b4.u[0];
        acc[2 * jj + 1] = b4.u[1];
    }

    for (int kb = 0; kb < 64; kb += 4) {
        float4 mv4 = *(const float4*)(m + kb);
        float4 xv4 = *(const float4*)(xi + kb);
        float mvs[4] = {mv4.x, mv4.y, mv4.z, mv4.w};
        float xvs[4] = {xv4.x, xv4.y, xv4.z, xv4.w};
#pragma unroll
        for (int kk = 0; kk < 4; kk++) {
            int k = kb + kk;
            ull mv2 = dup2(mvs[kk]);
            ull xv2 = dup2(xvs[kk]);
            const float4* wl4 = (const float4*)(s_wl + k * 64);
            const float4* wr4 = (const float4*)(s_wr + k * 64);
#pragma unroll
            for (int jj = 0; jj < 16; jj++) {
                F4U wa; wa.f4 = wl4[jj];
                F4U wb; wb.f4 = wr4[jj];
                acc[2 * jj]     = ffma2(wa.u[0], mv2, acc[2 * jj]);
                acc[2 * jj + 1] = ffma2(wa.u[1], mv2, acc[2 * jj + 1]);
                acc[2 * jj]     = ffma2(wb.u[0], xv2, acc[2 * jj]);
                acc[2 * jj + 1] = ffma2(wb.u[1], xv2, acc[2 * jj + 1]);
            }
        }
    }

    // relu -> store h1; fused p = h1 @ w2_l
    ull p[16];
#pragma unroll
    for (int jj = 0; jj < 16; jj++) p[jj] = 0ULL;

    float* oh = g_h1 + (size_t)i * 64;
#pragma unroll
    for (int jj = 0; jj < 32; jj++) {
        float lo = fmaxf(lo32(acc[jj]), 0.f);
        float hi = fmaxf(hi32(acc[jj]), 0.f);
        *(float2*)(oh + 2 * jj) = make_float2(lo, hi);
        ull hlo = dup2(lo), hhi = dup2(hi);
        const float4* wlo = (const float4*)(s_w2l + (2 * jj) * 32);
        const float4* whi = (const float4*)(s_w2l + (2 * jj + 1) * 32);
#pragma unroll
        for (int t = 0; t < 8; t++) {
            F4U wa; wa.f4 = wlo[t];
            F4U wb; wb.f4 = whi[t];
            p[2 * t]     = ffma2(wa.u[0], hlo, p[2 * t]);
            p[2 * t + 1] = ffma2(wa.u[1], hlo, p[2 * t + 1]);
            p[2 * t]     = ffma2(wb.u[0], hhi, p[2 * t]);
            p[2 * t + 1] = ffma2(wb.u[1], hhi, p[2 * t + 1]);
        }
    }
    unsigned* op = g_ph + (size_t)i * 16;
#pragma unroll
    for (int t = 0; t < 16; t++)
        op[t] = f2_to_h2(lo32(p[t]), hi32(p[t]));
}

// h2 = relu(mean2 + b2 + h1 @ w2_r); out = relu(h2@wc1+bc1)@wc2 + bc2
__global__ __launch_bounds__(128) void k_update2(const float* __restrict__ w2r,
                                                 const float* __restrict__ b2,
                                                 const float* __restrict__ wc1,
                                                 const float* __restrict__ bc1,
                                                 const float* __restrict__ wc2,
                                                 const float* __restrict__ bc2,
                                                 float* __restrict__ out) {
    __shared__ float s_wr[64 * 32], s_b2[32];
    __shared__ float s_wc1[32 * 16], s_bc1[16], s_wc2[16 * 2], s_bc2[2];
    for (int idx = threadIdx.x; idx < 2048; idx += 128) s_wr[idx] = w2r[idx];
    for (int idx = threadIdx.x; idx < 512; idx += 128) s_wc1[idx] = wc1[idx];
    if (threadIdx.x < 32) s_b2[threadIdx.x]  = b2[threadIdx.x];
    if (threadIdx.x < 32) s_wc2[threadIdx.x] = wc2[threadIdx.x];
    if (threadIdx.x < 16) s_bc1[threadIdx.x] = bc1[threadIdx.x];
    if (threadIdx.x < 2)  s_bc2[threadIdx.x] = bc2[threadIdx.x];
    __syncthreads();

    int i = blockIdx.x * blockDim.x + threadIdx.x;
    if (i >= NN) return;
    const float* m2 = g_mean2 + (size_t)i * 32;
    const float* hi = g_h1    + (size_t)i * 64;

    ull acc[16];
#pragma unroll
    for (int jj = 0; jj < 8; jj++) {
        F4U m4; m4.f4 = ((const float4*)m2)[jj];
        F4U b4; b4.f4 = ((const float4*)s_b2)[jj];
        acc[2 * jj]     = pack2(m4.f[0] + b4.f[0], m4.f[1] + b4.f[1]);
        acc[2 * jj + 1] = pack2(m4.f[2] + b4.f[2], m4.f[3] + b4.f[3]);
    }

    for (int kb = 0; kb < 64; kb += 4) {
        float4 hv4 = *(const float4*)(hi + kb);
        float hvs[4] = {hv4.x, hv4.y, hv4.z, hv4.w};
#pragma unroll
        for (int kk = 0; kk < 4; kk++) {
            ull hv2 = dup2(hvs[kk]);
            const float4* wr4 = (const float4*)(s_wr + (kb + kk) * 32);
#pragma unroll
            for (int t = 0; t < 8; t++) {
                F4U wa; wa.f4 = wr4[t];
                acc[2 * t]     = ffma2(wa.u[0], hv2, acc[2 * t]);
                acc[2 * t + 1] = ffma2(wa.u[1], hv2, acc[2 * t + 1]);
            }
        }
    }

    // classifier head
    ull c1[8];
#pragma unroll
    for (int t = 0; t < 4; t++) {
        F4U b4; b4.f4 = ((const float4*)s_bc1)[t];
        c1[2 * t]     = b4.u[0];
        c1[2 * t + 1] = b4.u[1];
    }
#pragma unroll
    for (int jj = 0; jj < 16; jj++) {
        float lo = fmaxf(lo32(acc[jj]), 0.f);
        float hi2 = fmaxf(hi32(acc[jj]), 0.f);
        ull hlo = dup2(lo), hhi = dup2(hi2);
        const float4* wlo = (const float4*)(s_wc1 + (2 * jj) * 16);
        const float4* whi = (const float4*)(s_wc1 + (2 * jj + 1) * 16);
#pragma unroll
        for (int t = 0; t < 4; t++) {
            F4U wa; wa.f4 = wlo[t];
            F4U wb; wb.f4 = whi[t];
            c1[2 * t]     = ffma2(wa.u[0], hlo, c1[2 * t]);
            c1[2 * t + 1] = ffma2(wa.u[1], hlo, c1[2 * t + 1]);
            c1[2 * t]     = ffma2(wb.u[0], hhi, c1[2 * t]);
            c1[2 * t + 1] = ffma2(wb.u[1], hhi, c1[2 * t + 1]);
        }
    }
    float o0 = s_bc2[0], o1 = s_bc2[1];
#pragma unroll
    for (int t = 0; t < 8; t++) {
        float h0 = fmaxf(lo32(c1[t]), 0.f);
        float h1v = fmaxf(hi32(c1[t]), 0.f);
        o0 += h0 * s_wc2[(2 * t) * 2 + 0] + h1v * s_wc2[(2 * t + 1) * 2 + 0];
        o1 += h0 * s_wc2[(2 * t) * 2 + 1] + h1v * s_wc2[(2 * t + 1) * 2 + 1];
    }
    *(float2*)(out + (size_t)i * 2) = make_float2(o0, o1);
}

// ------------------------------------------------------------------- launch
extern "C" void kernel_launch(void* const* d_in, const int* in_sizes, int n_in,
                              void* d_out, int out_size) {
    const float* x    = (const float*)d_in[0];
    const int*   ei   = (const int*)d_in[1];
    const int4*  src4 = (const int4*)ei;
    const int4*  dst4 = (const int4*)(ei + NE);
    const float* w1l = (const float*)d_in[2];
    const float* w1r = (const float*)d_in[3];
    const float* b1  = (const float*)d_in[4];
    const float* w2l = (const float*)d_in[5];
    const float* w2r = (const float*)d_in[6];
    const float* b2  = (const float*)d_in[7];
    const float* wc1 = (const float*)d_in[8];
    const float* bc1 = (const float*)d_in[9];
    const float* wc2 = (const float*)d_in[10];
    const float* bc2 = (const float*)d_in[11];
    float* out = (float*)d_out;

    // CSR build + staging: memset -> fused(stage+hist) -> scan -> scatter
    void* cp = nullptr;
    cudaGetSymbolAddress(&cp, g_counts);
    cudaMemsetAsync(cp, 0, NN * sizeof(int));
    k_stage_hist<<<(NN * 8 + 255) / 256, 256>>>((const float4*)x, dst4);
    k_scan<<<NCHUNK, CHUNK>>>();
    k_scatter<<<(NE / 8 + 255) / 256, 256>>>(src4, dst4);

    // Layer 1 (+ fused p = h1 @ w2_l, stored fp16)
    k_aggregate1<<<(NN * 32 + 255) / 256, 256>>>();
    k_update1<<<(NN + 127) / 128, 128>>>(x, w1l, w1r, b1, w2l);

    // Layer 2 + classifier
    k_aggregate2<<<(NN * 32 + 255) / 256, 256>>>();
    k_update2<<<(NN + 127) / 128, 128>>>(w2r, b2, wc1, bc1, wc2, bc2, out);
}

// round 16
// speedup vs baseline: 1.0823x; 1.0319x over previous
#include <cuda_runtime.h>
#include <cuda_fp16.h>

// HydraGNN: 2x SAGEConv(mean) + MLP head, fp32.
// R16 = R15 + HADD2 packed partial accumulation in both aggregations
// (4 HADD2 per 8-channel gather instead of 8 cvt + 8 FADD; fp32 flush per
// 32-edge chunk). fp16-staged x and p, broadcast-index gathers, f32x2 GEMMs.

#define NN 50000
#define NE 800000
#define CHUNK 512
#define NCHUNK ((NN + CHUNK - 1) / CHUNK)   // 98

typedef unsigned long long ull;

__device__ int g_counts[NN];
__device__ int g_row_start[NN + 1];
__device__ int g_row_fill[NN];
__device__ int g_csr_src[NE];
__device__ __align__(16) unsigned g_xh[NN * 32];  // x in fp16: 64ch = 128B/row
__device__ __align__(16) unsigned g_ph[NN * 16];  // p in fp16: 32ch = 64B/row
__device__ __align__(16) float g_mean[NN * 64];   // layer-1 mean (fp32)
__device__ __align__(16) float g_h1[NN * 64];     // relu(layer1)
__device__ __align__(16) float g_mean2[NN * 32];  // mean of p (fp32)

// ---------------------------------------------------------------- helpers
__device__ __forceinline__ ull ffma2(ull a, ull b, ull c) {
    ull d;
    asm("fma.rn.f32x2 %0, %1, %2, %3;" : "=l"(d) : "l"(a), "l"(b), "l"(c));
    return d;
}
__device__ __forceinline__ ull dup2(float v) {
    ull r; unsigned u = __float_as_uint(v);
    asm("mov.b64 %0, {%1, %1};" : "=l"(r) : "r"(u));
    return r;
}
__device__ __forceinline__ ull pack2(float lo, float hi) {
    ull r;
    asm("mov.b64 %0, {%1, %2};" : "=l"(r)
        : "r"(__float_as_uint(lo)), "r"(__float_as_uint(hi)));
    return r;
}
__device__ __forceinline__ float lo32(ull a) { return __uint_as_float((unsigned)a); }
__device__ __forceinline__ float hi32(ull a) { return __uint_as_float((unsigned)(a >> 32)); }
union F4U { float4 f4; ull u[2]; float f[4]; };

__device__ __forceinline__ unsigned f2_to_h2(float lo, float hi) {
    __half2 h = __float22half2_rn(make_float2(lo, hi));
    return *(unsigned*)&h;
}

// packed fp16 partial accumulation: 4 HADD2 per 8-channel gather
__device__ __forceinline__ void hacc4(__half2* h, const uint4& v) {
    h[0] = __hadd2(h[0], *(const __half2*)&v.x);
    h[1] = __hadd2(h[1], *(const __half2*)&v.y);
    h[2] = __hadd2(h[2], *(const __half2*)&v.z);
    h[3] = __hadd2(h[3], *(const __half2*)&v.w);
}
// flush fp16 partials into two fp32 float4 accumulators
__device__ __forceinline__ void hflush(float4& f0, float4& f1, const __half2* h) {
    float2 t;
    t = __half22float2(h[0]); f0.x += t.x; f0.y += t.y;
    t = __half22float2(h[1]); f0.z += t.x; f0.w += t.y;
    t = __half22float2(h[2]); f1.x += t.x; f1.y += t.y;
    t = __half22float2(h[3]); f1.z += t.x; f1.w += t.y;
}

// --------------------------------------------- fused x->fp16 staging + hist
__global__ void k_stage_hist(const float4* __restrict__ x4,
                             const int4* __restrict__ dst4) {
    int i = blockIdx.x * blockDim.x + threadIdx.x;
    if (i < NN * 8) {
        float4 a = x4[2 * i];
        float4 b = x4[2 * i + 1];
        uint4 o;
        o.x = f2_to_h2(a.x, a.y);
        o.y = f2_to_h2(a.z, a.w);
        o.z = f2_to_h2(b.x, b.y);
        o.w = f2_to_h2(b.z, b.w);
        ((uint4*)g_xh)[i] = o;
    }
    if (i < NE / 4) {
        int4 d = dst4[i];
        atomicAdd(&g_counts[d.x], 1);
        atomicAdd(&g_counts[d.y], 1);
        atomicAdd(&g_counts[d.z], 1);
        atomicAdd(&g_counts[d.w], 1);
    }
}

// ---------------------------------------------------------------- CSR build
__global__ __launch_bounds__(CHUNK) void k_scan() {
    __shared__ int sh[CHUNK];
    __shared__ int s_prefix;
    int b = blockIdx.x, t = threadIdx.x;
    int base = b * CHUNK;
    int partial = 0;
    for (int k = t; k < base; k += CHUNK) partial += g_counts[k];
    sh[t] = partial;
    __syncthreads();
#pragma unroll
    for (int off = CHUNK >> 1; off > 0; off >>= 1) {
        if (t < off) sh[t] += sh[t + off];
        __syncthreads();
    }
    if (t == 0) s_prefix = sh[0];
    __syncthreads();

    int i = base + t;
    int v = (i < NN) ? g_counts[i] : 0;
    sh[t] = v;
    __syncthreads();
#pragma unroll
    for (int off = 1; off < CHUNK; off <<= 1) {
        int tv = (t >= off) ? sh[t - off] : 0;
        __syncthreads();
        sh[t] += tv;
        __syncthreads();
    }
    if (i < NN) {
        int excl = s_prefix + sh[t] - v;
        g_row_start[i] = excl;
        g_row_fill[i]  = excl;
    }
    if (b == NCHUNK - 1 && t == CHUNK - 1) g_row_start[NN] = NE;
}

// Scatter: 8 edges per thread -> 8 independent atomic+store chains.
__global__ void k_scatter(const int4* __restrict__ src4,
                          const int4* __restrict__ dst4) {
    int e = blockIdx.x * blockDim.x + threadIdx.x;
    if (e < NE / 8) {
        int4 s0 = src4[e],          d0 = dst4[e];
        int4 s1 = src4[e + NE / 8], d1 = dst4[e + NE / 8];
        int p0 = atomicAdd(&g_row_fill[d0.x], 1);
        int p1 = atomicAdd(&g_row_fill[d0.y], 1);
        int p2 = atomicAdd(&g_row_fill[d0.z], 1);
        int p3 = atomicAdd(&g_row_fill[d0.w], 1);
        int p4 = atomicAdd(&g_row_fill[d1.x], 1);
        int p5 = atomicAdd(&g_row_fill[d1.y], 1);
        int p6 = atomicAdd(&g_row_fill[d1.z], 1);
        int p7 = atomicAdd(&g_row_fill[d1.w], 1);
        g_csr_src[p0] = s0.x;
        g_csr_src[p1] = s0.y;
        g_csr_src[p2] = s0.z;
        g_csr_src[p3] = s0.w;
        g_csr_src[p4] = s1.x;
        g_csr_src[p5] = s1.y;
        g_csr_src[p6] = s1.z;
        g_csr_src[p7] = s1.w;
    }
}

// ---------------------------------------------------- layer-1 aggregation
// Warp per node, fp16 rows (128B). Broadcast-index; quarter-warp per edge
// (lane = e4*8 + c8). HADD2 partial accumulation, fp32 flush per chunk.
__global__ __launch_bounds__(256) void k_aggregate1() {
    int w = (blockIdx.x * blockDim.x + threadIdx.x) >> 5;
    if (w >= NN) return;
    int lane = threadIdx.x & 31;
    int e4 = lane >> 3;          // 0..3: edge slot
    int c8 = lane & 7;           // uint4 chunk -> channels [8*c8, 8*c8+8)

    int s = __ldg(&g_row_start[w]), e = __ldg(&g_row_start[w + 1]);
    float4 a0 = make_float4(0.f, 0.f, 0.f, 0.f);
    float4 a1 = make_float4(0.f, 0.f, 0.f, 0.f);
    const __half2 hz = __float2half2_rn(0.f);

    for (int base = s; base < e; base += 32) {
        int n = e - base; if (n > 32) n = 32;
        int myidx = 0;
        if (base + lane < e) myidx = __ldg(&g_csr_src[base + lane]);
        __half2 A[4] = {hz, hz, hz, hz};
        __half2 B[4] = {hz, hz, hz, hz};
        for (int t2 = 0; t2 < n; t2 += 8) {
            int ta = t2 + e4;
            int tb = t2 + 4 + e4;
            int ia = __shfl_sync(0xffffffffu, myidx, ta & 31);
            int ib = __shfl_sync(0xffffffffu, myidx, tb & 31);
            if (ta < n) {
                uint4 v = ((const uint4*)(g_xh + (size_t)ia * 32))[c8];
                hacc4(A, v);
            }
            if (tb < n) {
                uint4 v = ((const uint4*)(g_xh + (size_t)ib * 32))[c8];
                hacc4(B, v);
            }
        }
        hflush(a0, a1, A);
        hflush(a0, a1, B);
    }
#pragma unroll
    for (int off = 8; off <= 16; off <<= 1) {
        a0.x += __shfl_xor_sync(0xffffffffu, a0.x, off);
        a0.y += __shfl_xor_sync(0xffffffffu, a0.y, off);
        a0.z += __shfl_xor_sync(0xffffffffu, a0.z, off);
        a0.w += __shfl_xor_sync(0xffffffffu, a0.w, off);
        a1.x += __shfl_xor_sync(0xffffffffu, a1.x, off);
        a1.y += __shfl_xor_sync(0xffffffffu, a1.y, off);
        a1.z += __shfl_xor_sync(0xffffffffu, a1.z, off);
        a1.w += __shfl_xor_sync(0xffffffffu, a1.w, off);
    }
    if (lane < 8) {
        float inv = 1.0f / fmaxf((float)(e - s), 1.0f);
        float4* o = (float4*)(g_mean + (size_t)w * 64 + c8 * 8);
        o[0] = make_float4(a0.x * inv, a0.y * inv, a0.z * inv, a0.w * inv);
        o[1] = make_float4(a1.x * inv, a1.y * inv, a1.z * inv, a1.w * inv);
    }
}

// ---------------------------------------------------- layer-2 aggregation
// Warp per node, fp16 p rows (64B). Eighth-warp per edge (lane = e8*4 + c4).
// HADD2 partial accumulation, fp32 flush per chunk.
__global__ __launch_bounds__(256) void k_aggregate2() {
    int w = (blockIdx.x * blockDim.x + threadIdx.x) >> 5;
    if (w >= NN) return;
    int lane = threadIdx.x & 31;
    int e8 = lane >> 2;          // 0..7: edge slot
    int c4 = lane & 3;           // uint4 chunk -> channels [8*c4, 8*c4+8)

    int s = __ldg(&g_row_start[w]), e = __ldg(&g_row_start[w + 1]);
    float4 a0 = make_float4(0.f, 0.f, 0.f, 0.f);
    float4 a1 = make_float4(0.f, 0.f, 0.f, 0.f);
    const __half2 hz = __float2half2_rn(0.f);

    for (int base = s; base < e; base += 32) {
        int n = e - base; if (n > 32) n = 32;
        int myidx = 0;
        if (base + lane < e) myidx = __ldg(&g_csr_src[base + lane]);
        __half2 A[4] = {hz, hz, hz, hz};
        __half2 B[4] = {hz, hz, hz, hz};
        for (int t2 = 0; t2 < n; t2 += 16) {
            int ta = t2 + e8;
            int tb = t2 + 8 + e8;
            int ia = __shfl_sync(0xffffffffu, myidx, ta & 31);
            int ib = __shfl_sync(0xffffffffu, myidx, tb & 31);
            if (ta < n) {
                uint4 v = ((const uint4*)(g_ph + (size_t)ia * 16))[c4];
                hacc4(A, v);
            }
            if (tb < n) {
                uint4 v = ((const uint4*)(g_ph + (size_t)ib * 16))[c4];
                hacc4(B, v);
            }
        }
        hflush(a0, a1, A);
        hflush(a0, a1, B);
    }
#pragma unroll
    for (int off = 4; off <= 16; off <<= 1) {
        a0.x += __shfl_xor_sync(0xffffffffu, a0.x, off);
        a0.y += __shfl_xor_sync(0xffffffffu, a0.y, off);
        a0.z += __shfl_xor_sync(0xffffffffu, a0.z, off);
        a0.w += __shfl_xor_sync(0xffffffffu, a0.w, off);
        a1.x += __shfl_xor_sync(0xffffffffu, a1.x, off);
        a1.y += __shfl_xor_sync(0xffffffffu, a1.y, off);
        a1.z += __shfl_xor_sync(0xffffffffu, a1.z, off);
        a1.w += __shfl_xor_sync(0xffffffffu, a1.w, off);
    }
    if (lane < 4) {
        float inv = 1.0f / fmaxf((float)(e - s), 1.0f);
        float4* o = (float4*)(g_mean2 + (size_t)w * 32 + c4 * 8);
        o[0] = make_float4(a0.x * inv, a0.y * inv, a0.z * inv, a0.w * inv);
        o[1] = make_float4(a1.x * inv, a1.y * inv, a1.z * inv, a1.w * inv);
    }
}

// ------------------------------------------------------------- update GEMMs
// h1 = relu(mean @ w1_l + x @ w1_r + b1);  p = h1 @ w2_l  (stored fp16)
__global__ __launch_bounds__(128) void k_update1(const float* __restrict__ x,
                                                 const float* __restrict__ wl,
                                                 const float* __restrict__ wr,
                                                 const float* __restrict__ b,
                                                 const float* __restrict__ w2l) {
    __shared__ float s_wl[64 * 64], s_wr[64 * 64], s_w2l[64 * 32], s_b[64];
    for (int idx = threadIdx.x; idx < 4096; idx += 128) {
        s_wl[idx] = wl[idx];
        s_wr[idx] = wr[idx];
    }
    for (int idx = threadIdx.x; idx < 2048; idx += 128) s_w2l[idx] = w2l[idx];
    if (threadIdx.x < 64) s_b[threadIdx.x] = b[threadIdx.x];
    __syncthreads();

    int i = blockIdx.x * blockDim.x + threadIdx.x;
    if (i >= NN) return;
    const float* m  = g_mean + (size_t)i * 64;
    const float* xi = x      + (size_t)i * 64;

    ull acc[32];
#pragma unroll
    for (int jj = 0; jj < 16; jj++) {
        F4U b4; b4.f4 = ((const float4*)s_b)[jj];
        acc[2 * jj]     = b4.u[0];
        acc[2 * jj + 1] = b4.u[1];
    }

    for (int kb = 0; kb < 64; kb += 4) {
        float4 mv4 = *(const float4*)(m + kb);
        float4 xv4 = *(const float4*)(xi + kb);
        float mvs[4] = {mv4.x, mv4.y, mv4.z, mv4.w};
        float xvs[4] = {xv4.x, xv4.y, xv4.z, xv4.w};
#pragma unroll
        for (int kk = 0; kk < 4; kk++) {
            int k = kb + kk;
            ull mv2 = dup2(mvs[kk]);
            ull xv2 = dup2(xvs[kk]);
            const float4* wl4 = (const float4*)(s_wl + k * 64);
            const float4* wr4 = (const float4*)(s_wr + k * 64);
#pragma unroll
            for (int jj = 0; jj < 16; jj++) {
                F4U wa; wa.f4 = wl4[jj];
                F4U wb; wb.f4 = wr4[jj];
                acc[2 * jj]     = ffma2(wa.u[0], mv2, acc[2 * jj]);
                acc[2 * jj + 1] = ffma2(wa.u[1], mv2, acc[2 * jj + 1]);
                acc[2 * jj]     = ffma2(wb.u[0], xv2, acc[2 * jj]);
                acc[2 * jj + 1] = ffma2(wb.u[1], xv2, acc[2 * jj + 1]);
            }
        }
    }

    // relu -> store h1; fused p = h1 @ w2_l
    ull p[16];
#pragma unroll
    for (int jj = 0; jj < 16; jj++) p[jj] = 0ULL;

    float* oh = g_h1 + (size_t)i * 64;
#pragma unroll
    for (int jj = 0; jj < 32; jj++) {
        float lo = fmaxf(lo32(acc[jj]), 0.f);
        float hi = fmaxf(hi32(acc[jj]), 0.f);
        *(float2*)(oh + 2 * jj) = make_float2(lo, hi);
        ull hlo = dup2(lo), hhi = dup2(hi);
        const float4* wlo = (const float4*)(s_w2l + (2 * jj) * 32);
        const float4* whi = (const float4*)(s_w2l + (2 * jj + 1) * 32);
#pragma unroll
        for (int t = 0; t < 8; t++) {
            F4U wa; wa.f4 = wlo[t];
            F4U wb; wb.f4 = whi[t];
            p[2 * t]     = ffma2(wa.u[0], hlo, p[2 * t]);
            p[2 * t + 1] = ffma2(wa.u[1], hlo, p[2 * t + 1]);
            p[2 * t]     = ffma2(wb.u[0], hhi, p[2 * t]);
            p[2 * t + 1] = ffma2(wb.u[1], hhi, p[2 * t + 1]);
        }
    }
    unsigned* op = g_ph + (size_t)i * 16;
#pragma unroll
    for (int t = 0; t < 16; t++)
        op[t] = f2_to_h2(lo32(p[t]), hi32(p[t]));
}

// h2 = relu(mean2 + b2 + h1 @ w2_r); out = relu(h2@wc1+bc1)@wc2 + bc2
__global__ __launch_bounds__(128) void k_update2(const float* __restrict__ w2r,
                                                 const float* __restrict__ b2,
                                                 const float* __restrict__ wc1,
                                                 const float* __restrict__ bc1,
                                                 const float* __restrict__ wc2,
                                                 const float* __restrict__ bc2,
                                                 float* __restrict__ out) {
    __shared__ float s_wr[64 * 32], s_b2[32];
    __shared__ float s_wc1[32 * 16], s_bc1[16], s_wc2[16 * 2], s_bc2[2];
    for (int idx = threadIdx.x; idx < 2048; idx += 128) s_wr[idx] = w2r[idx];
    for (int idx = threadIdx.x; idx < 512; idx += 128) s_wc1[idx] = wc1[idx];
    if (threadIdx.x < 32) s_b2[threadIdx.x]  = b2[threadIdx.x];
    if (threadIdx.x < 32) s_wc2[threadIdx.x] = wc2[threadIdx.x];
    if (threadIdx.x < 16) s_bc1[threadIdx.x] = bc1[threadIdx.x];
    if (threadIdx.x < 2)  s_bc2[threadIdx.x] = bc2[threadIdx.x];
    __syncthreads();

    int i = blockIdx.x * blockDim.x + threadIdx.x;
    if (i >= NN) return;
    const float* m2 = g_mean2 + (size_t)i * 32;
    const float* hi = g_h1    + (size_t)i * 64;

    ull acc[16];
#pragma unroll
    for (int jj = 0; jj < 8; jj++) {
        F4U m4; m4.f4 = ((const float4*)m2)[jj];
        F4U b4; b4.f4 = ((const float4*)s_b2)[jj];
        acc[2 * jj]     = pack2(m4.f[0] + b4.f[0], m4.f[1] + b4.f[1]);
        acc[2 * jj + 1] = pack2(m4.f[2] + b4.f[2], m4.f[3] + b4.f[3]);
    }

    for (int kb = 0; kb < 64; kb += 4) {
        float4 hv4 = *(const float4*)(hi + kb);
        float hvs[4] = {hv4.x, hv4.y, hv4.z, hv4.w};
#pragma unroll
        for (int kk = 0; kk < 4; kk++) {
            ull hv2 = dup2(hvs[kk]);
            const float4* wr4 = (const float4*)(s_wr + (kb + kk) * 32);
#pragma unroll
            for (int t = 0; t < 8; t++) {
                F4U wa; wa.f4 = wr4[t];
                acc[2 * t]     = ffma2(wa.u[0], hv2, acc[2 * t]);
                acc[2 * t + 1] = ffma2(wa.u[1], hv2, acc[2 * t + 1]);
            }
        }
    }

    // classifier head
    ull c1[8];
#pragma unroll
    for (int t = 0; t < 4; t++) {
        F4U b4; b4.f4 = ((const float4*)s_bc1)[t];
        c1[2 * t]     = b4.u[0];
        c1[2 * t + 1] = b4.u[1];
    }
#pragma unroll
    for (int jj = 0; jj < 16; jj++) {
        float lo = fmaxf(lo32(acc[jj]), 0.f);
        float hi2 = fmaxf(hi32(acc[jj]), 0.f);
        ull hlo = dup2(lo), hhi = dup2(hi2);
        const float4* wlo = (const float4*)(s_wc1 + (2 * jj) * 16);
        const float4* whi = (const float4*)(s_wc1 + (2 * jj + 1) * 16);
#pragma unroll
        for (int t = 0; t < 4; t++) {
            F4U wa; wa.f4 = wlo[t];
            F4U wb; wb.f4 = whi[t];
            c1[2 * t]     = ffma2(wa.u[0], hlo, c1[2 * t]);
            c1[2 * t + 1] = ffma2(wa.u[1], hlo, c1[2 * t + 1]);
            c1[2 * t]     = ffma2(wb.u[0], hhi, c1[2 * t]);
            c1[2 * t + 1] = ffma2(wb.u[1], hhi, c1[2 * t + 1]);
        }
    }
    float o0 = s_bc2[0], o1 = s_bc2[1];
#pragma unroll
    for (int t = 0; t < 8; t++) {
        float h0 = fmaxf(lo32(c1[t]), 0.f);
        float h1v = fmaxf(hi32(c1[t]), 0.f);
        o0 += h0 * s_wc2[(2 * t) * 2 + 0] + h1v * s_wc2[(2 * t + 1) * 2 + 0];
        o1 += h0 * s_wc2[(2 * t) * 2 + 1] + h1v * s_wc2[(2 * t + 1) * 2 + 1];
    }
    *(float2*)(out + (size_t)i * 2) = make_float2(o0, o1);
}

// ------------------------------------------------------------------- launch
extern "C" void kernel_launch(void* const* d_in, const int* in_sizes, int n_in,
                              void* d_out, int out_size) {
    const float* x    = (const float*)d_in[0];
    const int*   ei   = (const int*)d_in[1];
    const int4*  src4 = (const int4*)ei;
    const int4*  dst4 = (const int4*)(ei + NE);
    const float* w1l = (const float*)d_in[2];
    const float* w1r = (const float*)d_in[3];
    const float* b1  = (const float*)d_in[4];
    const float* w2l = (const float*)d_in[5];
    const float* w2r = (const float*)d_in[6];
    const float* b2  = (const float*)d_in[7];
    const float* wc1 = (const float*)d_in[8];
    const float* bc1 = (const float*)d_in[9];
    const float* wc2 = (const float*)d_in[10];
    const float* bc2 = (const float*)d_in[11];
    float* out = (float*)d_out;

    // CSR build + staging: memset -> fused(stage+hist) -> scan -> scatter
    void* cp = nullptr;
    cudaGetSymbolAddress(&cp, g_counts);
    cudaMemsetAsync(cp, 0, NN * sizeof(int));
    k_stage_hist<<<(NN * 8 + 255) / 256, 256>>>((const float4*)x, dst4);
    k_scan<<<NCHUNK, CHUNK>>>();
    k_scatter<<<(NE / 8 + 255) / 256, 256>>>(src4, dst4);

    // Layer 1 (+ fused p = h1 @ w2_l, stored fp16)
    k_aggregate1<<<(NN * 32 + 255) / 256, 256>>>();
    k_update1<<<(NN + 127) / 128, 128>>>(x, w1l, w1r, b1, w2l);

    // Layer 2 + classifier
    k_aggregate2<<<(NN * 32 + 255) / 256, 256>>>();
    k_update2<<<(NN + 127) / 128, 128>>>(w2r, b2, wc1, bc1, wc2, bc2, out);
}

// round 17
// speedup vs baseline: 1.1626x; 1.0741x over previous
#include <cuda_runtime.h>
#include <cuda_fp16.h>

// HydraGNN: 2x SAGEConv(mean) + MLP head, fp32.
// R17 = R16 + multi-node warps in aggregation (4 nodes/warp L1, 8 nodes/warp
// L2; each lane owns its channels -> NO shuffle-reduction epilogue), memset
// node eliminated (scatter zeroes counts for next replay).

#define NN 50000
#define NE 800000
#define CHUNK 512
#define NCHUNK ((NN + CHUNK - 1) / CHUNK)   // 98

typedef unsigned long long ull;

__device__ int g_counts[NN];                // zero-init; re-zeroed by k_scatter
__device__ int g_row_start[NN + 1];
__device__ int g_row_fill[NN];
__device__ int g_csr_src[NE];
__device__ __align__(16) unsigned g_xh[NN * 32];  // x in fp16: 64ch = 128B/row
__device__ __align__(16) unsigned g_ph[NN * 16];  // p in fp16: 32ch = 64B/row
__device__ __align__(16) float g_mean[NN * 64];   // layer-1 mean (fp32)
__device__ __align__(16) float g_h1[NN * 64];     // relu(layer1)
__device__ __align__(16) float g_mean2[NN * 32];  // mean of p (fp32)

// ---------------------------------------------------------------- helpers
__device__ __forceinline__ ull ffma2(ull a, ull b, ull c) {
    ull d;
    asm("fma.rn.f32x2 %0, %1, %2, %3;" : "=l"(d) : "l"(a), "l"(b), "l"(c));
    return d;
}
__device__ __forceinline__ ull dup2(float v) {
    ull r; unsigned u = __float_as_uint(v);
    asm("mov.b64 %0, {%1, %1};" : "=l"(r) : "r"(u));
    return r;
}
__device__ __forceinline__ ull pack2(float lo, float hi) {
    ull r;
    asm("mov.b64 %0, {%1, %2};" : "=l"(r)
        : "r"(__float_as_uint(lo)), "r"(__float_as_uint(hi)));
    return r;
}
__device__ __forceinline__ float lo32(ull a) { return __uint_as_float((unsigned)a); }
__device__ __forceinline__ float hi32(ull a) { return __uint_as_float((unsigned)(a >> 32)); }
union F4U { float4 f4; ull u[2]; float f[4]; };

__device__ __forceinline__ unsigned f2_to_h2(float lo, float hi) {
    __half2 h = __float22half2_rn(make_float2(lo, hi));
    return *(unsigned*)&h;
}
// packed fp16 partial accumulation: 4 HADD2 per 8-channel gather
__device__ __forceinline__ void hacc4(__half2* h, const uint4& v) {
    h[0] = __hadd2(h[0], *(const __half2*)&v.x);
    h[1] = __hadd2(h[1], *(const __half2*)&v.y);
    h[2] = __hadd2(h[2], *(const __half2*)&v.z);
    h[3] = __hadd2(h[3], *(const __half2*)&v.w);
}
// flush fp16 partials into two fp32 float4 accumulators
__device__ __forceinline__ void hflush(float4& f0, float4& f1, const __half2* h) {
    float2 t;
    t = __half22float2(h[0]); f0.x += t.x; f0.y += t.y;
    t = __half22float2(h[1]); f0.z += t.x; f0.w += t.y;
    t = __half22float2(h[2]); f1.x += t.x; f1.y += t.y;
    t = __half22float2(h[3]); f1.z += t.x; f1.w += t.y;
}

// --------------------------------------------- fused x->fp16 staging + hist
__global__ void k_stage_hist(const float4* __restrict__ x4,
                             const int4* __restrict__ dst4) {
    int i = blockIdx.x * blockDim.x + threadIdx.x;
    if (i < NN * 8) {
        float4 a = x4[2 * i];
        float4 b = x4[2 * i + 1];
        uint4 o;
        o.x = f2_to_h2(a.x, a.y);
        o.y = f2_to_h2(a.z, a.w);
        o.z = f2_to_h2(b.x, b.y);
        o.w = f2_to_h2(b.z, b.w);
        ((uint4*)g_xh)[i] = o;
    }
    if (i < NE / 4) {
        int4 d = dst4[i];
        atomicAdd(&g_counts[d.x], 1);
        atomicAdd(&g_counts[d.y], 1);
        atomicAdd(&g_counts[d.z], 1);
        atomicAdd(&g_counts[d.w], 1);
    }
}

// ---------------------------------------------------------------- CSR build
__global__ __launch_bounds__(CHUNK) void k_scan() {
    __shared__ int sh[CHUNK];
    __shared__ int s_prefix;
    int b = blockIdx.x, t = threadIdx.x;
    int base = b * CHUNK;
    int partial = 0;
    for (int k = t; k < base; k += CHUNK) partial += g_counts[k];
    sh[t] = partial;
    __syncthreads();
#pragma unroll
    for (int off = CHUNK >> 1; off > 0; off >>= 1) {
        if (t < off) sh[t] += sh[t + off];
        __syncthreads();
    }
    if (t == 0) s_prefix = sh[0];
    __syncthreads();

    int i = base + t;
    int v = (i < NN) ? g_counts[i] : 0;
    sh[t] = v;
    __syncthreads();
#pragma unroll
    for (int off = 1; off < CHUNK; off <<= 1) {
        int tv = (t >= off) ? sh[t - off] : 0;
        __syncthreads();
        sh[t] += tv;
        __syncthreads();
    }
    if (i < NN) {
        int excl = s_prefix + sh[t] - v;
        g_row_start[i] = excl;
        g_row_fill[i]  = excl;
    }
    if (b == NCHUNK - 1 && t == CHUNK - 1) g_row_start[NN] = NE;
}

// Scatter: 8 edges per thread -> 8 independent atomic+store chains.
// ALSO zeroes g_counts for the next graph replay (last reader was k_scan).
__global__ void k_scatter(const int4* __restrict__ src4,
                          const int4* __restrict__ dst4) {
    int e = blockIdx.x * blockDim.x + threadIdx.x;
    if (e < NN) g_counts[e] = 0;   // NE/8 = 100000 >= NN, full coverage
    if (e < NE / 8) {
        int4 s0 = src4[e],          d0 = dst4[e];
        int4 s1 = src4[e + NE / 8], d1 = dst4[e + NE / 8];
        int p0 = atomicAdd(&g_row_fill[d0.x], 1);
        int p1 = atomicAdd(&g_row_fill[d0.y], 1);
        int p2 = atomicAdd(&g_row_fill[d0.z], 1);
        int p3 = atomicAdd(&g_row_fill[d0.w], 1);
        int p4 = atomicAdd(&g_row_fill[d1.x], 1);
        int p5 = atomicAdd(&g_row_fill[d1.y], 1);
        int p6 = atomicAdd(&g_row_fill[d1.z], 1);
        int p7 = atomicAdd(&g_row_fill[d1.w], 1);
        g_csr_src[p0] = s0.x;
        g_csr_src[p1] = s0.y;
        g_csr_src[p2] = s0.z;
        g_csr_src[p3] = s0.w;
        g_csr_src[p4] = s1.x;
        g_csr_src[p5] = s1.y;
        g_csr_src[p6] = s1.z;
        g_csr_src[p7] = s1.w;
    }
}

// ---------------------------------------------------- layer-1 aggregation
// FOUR nodes per warp: lane = g*8 + c8; 8-lane group owns one node, lane owns
// channels [8*c8, 8*c8+8) exclusively (fp16 row = 8 lanes x 16B). One warp
// LDG.128 covers 4 edges' full rows. NO shuffle reduction in the epilogue.
__global__ __launch_bounds__(256) void k_aggregate1() {
    int warp = (blockIdx.x * blockDim.x + threadIdx.x) >> 5;
    int lane = threadIdx.x & 31;
    int g  = lane >> 3;           // group 0..3 -> node slot
    int c8 = lane & 7;            // uint4 chunk -> channels [8*c8, 8*c8+8)
    int w = warp * 4 + g;
    if (w >= NN) return;          // NN%4==0: uniform per warp

    int s = __ldg(&g_row_start[w]), e = __ldg(&g_row_start[w + 1]);
    int deg = e - s;
    // warp-uniform loop bound = max degree among the 4 packed nodes
    int m = deg;
#pragma unroll
    for (int off = 16; off > 0; off >>= 1)
        m = max(m, __shfl_xor_sync(0xffffffffu, m, off));

    float4 a0 = make_float4(0.f, 0.f, 0.f, 0.f);
    float4 a1 = make_float4(0.f, 0.f, 0.f, 0.f);
    const __half2 hz = __float2half2_rn(0.f);

    for (int base = 0; base < m; base += 8) {
        int myidx = 0;
        if (base + c8 < deg) myidx = __ldg(&g_csr_src[s + base + c8]);
        int nn = deg - base;      // may be <=0 for finished groups
        __half2 A[4] = {hz, hz, hz, hz};
#pragma unroll
        for (int t = 0; t < 8; t++) {
            int ia = __shfl_sync(0xffffffffu, myidx, (lane & 24) + t);
            if (t < nn) {
                uint4 v = ((const uint4*)(g_xh + (size_t)ia * 32))[c8];
                hacc4(A, v);
            }
        }
        hflush(a0, a1, A);
    }
    float inv = 1.0f / fmaxf((float)deg, 1.0f);
    float4* o = (float4*)(g_mean + (size_t)w * 64 + c8 * 8);
    o[0] = make_float4(a0.x * inv, a0.y * inv, a0.z * inv, a0.w * inv);
    o[1] = make_float4(a1.x * inv, a1.y * inv, a1.z * inv, a1.w * inv);
}

// ---------------------------------------------------- layer-2 aggregation
// EIGHT nodes per warp: lane = g*4 + c4; 4-lane group owns one node (fp16 p
// row = 64B = 4 lanes x 16B). One warp LDG.128 covers 8 edges' full rows.
__global__ __launch_bounds__(256) void k_aggregate2() {
    int warp = (blockIdx.x * blockDim.x + threadIdx.x) >> 5;
    int lane = threadIdx.x & 31;
    int g  = lane >> 2;           // group 0..7 -> node slot
    int c4 = lane & 3;            // uint4 chunk -> channels [8*c4, 8*c4+8)
    int w = warp * 8 + g;
    if (w >= NN) return;          // NN%8==0: uniform per warp

    int s = __ldg(&g_row_start[w]), e = __ldg(&g_row_start[w + 1]);
    int deg = e - s;
    int m = deg;
#pragma unroll
    for (int off = 16; off > 0; off >>= 1)
        m = max(m, __shfl_xor_sync(0xffffffffu, m, off));

    float4 a0 = make_float4(0.f, 0.f, 0.f, 0.f);
    float4 a1 = make_float4(0.f, 0.f, 0.f, 0.f);
    const __half2 hz = __float2half2_rn(0.f);

    for (int base = 0; base < m; base += 4) {
        int myidx = 0;
        if (base + c4 < deg) myidx = __ldg(&g_csr_src[s + base + c4]);
        int nn = deg - base;
        __half2 A[4] = {hz, hz, hz, hz};
#pragma unroll
        for (int t = 0; t < 4; t++) {
            int ia = __shfl_sync(0xffffffffu, myidx, (lane & 28) + t);
            if (t < nn) {
                uint4 v = ((const uint4*)(g_ph + (size_t)ia * 16))[c4];
                hacc4(A, v);
            }
        }
        hflush(a0, a1, A);
    }
    float inv = 1.0f / fmaxf((float)deg, 1.0f);
    float4* o = (float4*)(g_mean2 + (size_t)w * 32 + c4 * 8);
    o[0] = make_float4(a0.x * inv, a0.y * inv, a0.z * inv, a0.w * inv);
    o[1] = make_float4(a1.x * inv, a1.y * inv, a1.z * inv, a1.w * inv);
}

// ------------------------------------------------------------- update GEMMs
// h1 = relu(mean @ w1_l + x @ w1_r + b1);  p = h1 @ w2_l  (stored fp16)
__global__ __launch_bounds__(128) void k_update1(const float* __restrict__ x,
                                                 const float* __restrict__ wl,
                                                 const float* __restrict__ wr,
                                                 const float* __restrict__ b,
                                                 const float* __restrict__ w2l) {
    __shared__ float s_wl[64 * 64], s_wr[64 * 64], s_w2l[64 * 32], s_b[64];
    for (int idx = threadIdx.x; idx < 4096; idx += 128) {
        s_wl[idx] = wl[idx];
        s_wr[idx] = wr[idx];
    }
    for (int idx = threadIdx.x; idx < 2048; idx += 128) s_w2l[idx] = w2l[idx];
    if (threadIdx.x < 64) s_b[threadIdx.x] = b[threadIdx.x];
    __syncthreads();

    int i = blockIdx.x * blockDim.x + threadIdx.x;
    if (i >= NN) return;
    const float* m  = g_mean + (size_t)i * 64;
    const float* xi = x      + (size_t)i * 64;

    ull acc[32];
#pragma unroll
    for (int jj = 0; jj < 16; jj++) {
        F4U b4; b4.f4 = ((const float4*)s_b)[jj];
        acc[2 * jj]     = b4.u[0];
        acc[2 * jj + 1] = b4.u[1];
    }

    for (int kb = 0; kb < 64; kb += 4) {
        float4 mv4 = *(const float4*)(m + kb);
        float4 xv4 = *(const float4*)(xi + kb);
        float mvs[4] = {mv4.x, mv4.y, mv4.z, mv4.w};
        float xvs[4] = {xv4.x, xv4.y, xv4.z, xv4.w};
#pragma unroll
        for (int kk = 0; kk < 4; kk++) {
            int k = kb + kk;
            ull mv2 = dup2(mvs[kk]);
            ull xv2 = dup2(xvs[kk]);
            const float4* wl4 = (const float4*)(s_wl + k * 64);
            const float4* wr4 = (const float4*)(s_wr + k * 64);
#pragma unroll
            for (int jj = 0; jj < 16; jj++) {
                F4U wa; wa.f4 = wl4[jj];
                F4U wb; wb.f4 = wr4[jj];
                acc[2 * jj]     = ffma2(wa.u[0], mv2, acc[2 * jj]);
                acc[2 * jj + 1] = ffma2(wa.u[1], mv2, acc[2 * jj + 1]);
                acc[2 * jj]     = ffma2(wb.u[0], xv2, acc[2 * jj]);
                acc[2 * jj + 1] = ffma2(wb.u[1], xv2, acc[2 * jj + 1]);
            }
        }
    }

    // relu -> store h1; fused p = h1 @ w2_l
    ull p[16];
#pragma unroll
    for (int jj = 0; jj < 16; jj++) p[jj] = 0ULL;

    float* oh = g_h1 + (size_t)i * 64;
#pragma unroll
    for (int jj = 0; jj < 32; jj++) {
        float lo = fmaxf(lo32(acc[jj]), 0.f);
        float hi = fmaxf(hi32(acc[jj]), 0.f);
        *(float2*)(oh + 2 * jj) = make_float2(lo, hi);
        ull hlo = dup2(lo), hhi = dup2(hi);
        const float4* wlo = (const float4*)(s_w2l + (2 * jj) * 32);
        const float4* whi = (const float4*)(s_w2l + (2 * jj + 1) * 32);
#pragma unroll
        for (int t = 0; t < 8; t++) {
            F4U wa; wa.f4 = wlo[t];
            F4U wb; wb.f4 = whi[t];
            p[2 * t]     = ffma2(wa.u[0], hlo, p[2 * t]);
            p[2 * t + 1] = ffma2(wa.u[1], hlo, p[2 * t + 1]);
            p[2 * t]     = ffma2(wb.u[0], hhi, p[2 * t]);
            p[2 * t + 1] = ffma2(wb.u[1], hhi, p[2 * t + 1]);
        }
    }
    unsigned* op = g_ph + (size_t)i * 16;
#pragma unroll
    for (int t = 0; t < 16; t++)
        op[t] = f2_to_h2(lo32(p[t]), hi32(p[t]));
}

// h2 = relu(mean2 + b2 + h1 @ w2_r); out = relu(h2@wc1+bc1)@wc2 + bc2
__global__ __launch_bounds__(128) void k_update2(const float* __restrict__ w2r,
                                                 const float* __restrict__ b2,
                                                 const float* __restrict__ wc1,
                                                 const float* __restrict__ bc1,
                                                 const float* __restrict__ wc2,
                                                 const float* __restrict__ bc2,
                                                 float* __restrict__ out) {
    __shared__ float s_wr[64 * 32], s_b2[32];
    __shared__ float s_wc1[32 * 16], s_bc1[16], s_wc2[16 * 2], s_bc2[2];
    for (int idx = threadIdx.x; idx < 2048; idx += 128) s_wr[idx] = w2r[idx];
    for (int idx = threadIdx.x; idx < 512; idx += 128) s_wc1[idx] = wc1[idx];
    if (threadIdx.x < 32) s_b2[threadIdx.x]  = b2[threadIdx.x];
    if (threadIdx.x < 32) s_wc2[threadIdx.x] = wc2[threadIdx.x];
    if (threadIdx.x < 16) s_bc1[threadIdx.x] = bc1[threadIdx.x];
    if (threadIdx.x < 2)  s_bc2[threadIdx.x] = bc2[threadIdx.x];
    __syncthreads();

    int i = blockIdx.x * blockDim.x + threadIdx.x;
    if (i >= NN) return;
    const float* m2 = g_mean2 + (size_t)i * 32;
    const float* hi = g_h1    + (size_t)i * 64;

    ull acc[16];
#pragma unroll
    for (int jj = 0; jj < 8; jj++) {
        F4U m4; m4.f4 = ((const float4*)m2)[jj];
        F4U b4; b4.f4 = ((const float4*)s_b2)[jj];
        acc[2 * jj]     = pack2(m4.f[0] + b4.f[0], m4.f[1] + b4.f[1]);
        acc[2 * jj + 1] = pack2(m4.f[2] + b4.f[2], m4.f[3] + b4.f[3]);
    }

    for (int kb = 0; kb < 64; kb += 4) {
        float4 hv4 = *(const float4*)(hi + kb);
        float hvs[4] = {hv4.x, hv4.y, hv4.z, hv4.w};
#pragma unroll
        for (int kk = 0; kk < 4; kk++) {
            ull hv2 = dup2(hvs[kk]);
            const float4* wr4 = (const float4*)(s_wr + (kb + kk) * 32);
#pragma unroll
            for (int t = 0; t < 8; t++) {
                F4U wa; wa.f4 = wr4[t];
                acc[2 * t]     = ffma2(wa.u[0], hv2, acc[2 * t]);
                acc[2 * t + 1] = ffma2(wa.u[1], hv2, acc[2 * t + 1]);
            }
        }
    }

    // classifier head
    ull c1[8];
#pragma unroll
    for (int t = 0; t < 4; t++) {
        F4U b4; b4.f4 = ((const float4*)s_bc1)[t];
        c1[2 * t]     = b4.u[0];
        c1[2 * t + 1] = b4.u[1];
    }
#pragma unroll
    for (int jj = 0; jj < 16; jj++) {
        float lo = fmaxf(lo32(acc[jj]), 0.f);
        float hi2 = fmaxf(hi32(acc[jj]), 0.f);
        ull hlo = dup2(lo), hhi = dup2(hi2);
        const float4* wlo = (const float4*)(s_wc1 + (2 * jj) * 16);
        const float4* whi = (const float4*)(s_wc1 + (2 * jj + 1) * 16);
#pragma unroll
        for (int t = 0; t < 4; t++) {
            F4U wa; wa.f4 = wlo[t];
            F4U wb; wb.f4 = whi[t];
            c1[2 * t]     = ffma2(wa.u[0], hlo, c1[2 * t]);
            c1[2 * t + 1] = ffma2(wa.u[1], hlo, c1[2 * t + 1]);
            c1[2 * t]     = ffma2(wb.u[0], hhi, c1[2 * t]);
            c1[2 * t + 1] = ffma2(wb.u[1], hhi, c1[2 * t + 1]);
        }
    }
    float o0 = s_bc2[0], o1 = s_bc2[1];
#pragma unroll
    for (int t = 0; t < 8; t++) {
        float h0 = fmaxf(lo32(c1[t]), 0.f);
        float h1v = fmaxf(hi32(c1[t]), 0.f);
        o0 += h0 * s_wc2[(2 * t) * 2 + 0] + h1v * s_wc2[(2 * t + 1) * 2 + 0];
        o1 += h0 * s_wc2[(2 * t) * 2 + 1] + h1v * s_wc2[(2 * t + 1) * 2 + 1];
    }
    *(float2*)(out + (size_t)i * 2) = make_float2(o0, o1);
}

// ------------------------------------------------------------------- launch
extern "C" void kernel_launch(void* const* d_in, const int* in_sizes, int n_in,
                              void* d_out, int out_size) {
    const float* x    = (const float*)d_in[0];
    const int*   ei   = (const int*)d_in[1];
    const int4*  src4 = (const int4*)ei;
    const int4*  dst4 = (const int4*)(ei + NE);
    const float* w1l = (const float*)d_in[2];
    const float* w1r = (const float*)d_in[3];
    const float* b1  = (const float*)d_in[4];
    const float* w2l = (const float*)d_in[5];
    const float* w2r = (const float*)d_in[6];
    const float* b2  = (const float*)d_in[7];
    const float* wc1 = (const float*)d_in[8];
    const float* bc1 = (const float*)d_in[9];
    const float* wc2 = (const float*)d_in[10];
    const float* bc2 = (const float*)d_in[11];
    float* out = (float*)d_out;

    // CSR build + staging: fused(stage+hist) -> scan -> scatter(+count reset)
    // g_counts starts zeroed (static init on first call; k_scatter re-zeroes
    // it each replay after k_scan, its last reader, has consumed it).
    k_stage_hist<<<(NN * 8 + 255) / 256, 256>>>((const float4*)x, dst4);
    k_scan<<<NCHUNK, CHUNK>>>();
    k_scatter<<<(NE / 8 + 255) / 256, 256>>>(src4, dst4);

    // Layer 1 (+ fused p = h1 @ w2_l, stored fp16)
    k_aggregate1<<<((NN / 4) * 32 + 255) / 256, 256>>>();
    k_update1<<<(NN + 127) / 128, 128>>>(x, w1l, w1r, b1, w2l);

    // Layer 2 + classifier
    k_aggregate2<<<((NN / 8) * 32 + 255) / 256, 256>>>();
    k_update2<<<(NN + 127) / 128, 128>>>(w2r, b2, wc1, bc1, wc2, bc2, out);
}